// round 11
// baseline (speedup 1.0000x reference)
#include <cuda_runtime.h>
#include <cuda_fp16.h>
#include <math.h>
#include <stdint.h>

// ---------------- compile-time maxima (problem shapes are fixed) -------------
#define MAXN 10000
#define MAXE 50000
#define MAXB 512
#define H 64
#define HH 4096      // H*H
#define WID 128      // edge-MLP hidden width
#define GRU3 192     // 3*H
#define LST4 256     // 4*H
#define MAXTILES 391                      // ceil(MAXE/128)

// ---------------- device scratch (allocation-free rule: __device__ globals) --
// W_edge stored in mma-fragment order, 1 MB per 128-edge tile:
// half index = ((((tile*32 + I)*8 + wid)*8 + mf*2 + h)*32 + lane)*8 + k
__device__ __half g_WedgeH[(size_t)MAXTILES * 128 * HH];
__device__ __half g_hidH[(size_t)(MAXE + 128) * WID]; // edge MLP hidden fp16
__device__ __half g_W2H[HH * WID];                    // nn_W2 fp16
__device__ float g_x[MAXN * H];
__device__ float g_agg[MAXN * H];
__device__ float g_deg[MAXN];
// packed weights: float4 over 4 consecutive i for fixed output o (coalesced in o)
__device__ float4 g_rootP[16 * 64];           // [i4][o]
__device__ float4 g_giP[16 * 3 * 64];         // [i4][gate][o]
__device__ float4 g_ghP[16 * 3 * 64];
__device__ float g_lstmWihT[2 * H * LST4];
__device__ float g_lstmWhhT[H * LST4];

__device__ __forceinline__ float sigm(float v) { return 1.f / (1.f + expf(-v)); }
__device__ __forceinline__ float siluf(float v) { return v / (1.f + expf(-v)); }

__device__ __forceinline__ uint32_t smem_to_u32(const void* p) {
    uint32_t a;
    asm("{ .reg .u64 t; cvta.to.shared.u64 t, %1; cvt.u32.u64 %0, t; }" : "=r"(a) : "l"(p));
    return a;
}

// ---------------- mma.sync helpers -------------------------------------------
#define LDSM_X4(r, addr) \
    asm volatile("ldmatrix.sync.aligned.m8n8.x4.shared.b16 {%0,%1,%2,%3}, [%4];" \
        : "=r"((r)[0]), "=r"((r)[1]), "=r"((r)[2]), "=r"((r)[3]) : "r"(addr))
#define LDSM_X2(r, addr) \
    asm volatile("ldmatrix.sync.aligned.m8n8.x2.shared.b16 {%0,%1}, [%2];" \
        : "=r"((r)[0]), "=r"((r)[1]) : "r"(addr))
#define MMA_F16(c, a, b) \
    asm volatile("mma.sync.aligned.m16n8k16.row.col.f32.f16.f16.f32 " \
        "{%0,%1,%2,%3}, {%4,%5,%6,%7}, {%8,%9}, {%0,%1,%2,%3};" \
        : "+f"((c)[0]), "+f"((c)[1]), "+f"((c)[2]), "+f"((c)[3]) \
        : "r"((a)[0]), "r"((a)[1]), "r"((a)[2]), "r"((a)[3]), "r"((b)[0]), "r"((b)[1]))
#define CP_ASYNC16(s, g) \
    asm volatile("cp.async.cg.shared.global [%0], [%1], 16;" :: "r"(s), "l"(g))
#define CP_COMMIT() asm volatile("cp.async.commit_group;")
#define CP_WAIT1() asm volatile("cp.async.wait_group 1;" ::: "memory")
#define CP_WAIT0() asm volatile("cp.async.wait_group 0;" ::: "memory")

// smem geometry for the wedge GEMM (fp16, single product)
#define ATILE_B (128 * 136 * 2)        // 34816 B per 128x128 fp16 tile (272 B rows)
#define OFFA 0
#define OFFB(buf) (ATILE_B + (buf) * ATILE_B)
#define SMEM_WEDGE (3 * ATILE_B)       // 104448 B -> 2 CTAs/SM
#define JSPLIT 8                       // j-dim CTA split (4 iters each)

// ---------------- init A: node embed + deg/agg zero --------------------------
__global__ void k_init_node(const float* __restrict__ x, const float* __restrict__ flW,
                            const float* __restrict__ flb, int N) {
    int sub = threadIdx.x >> 6, o = threadIdx.x & 63;
    int n = blockIdx.x * 4 + sub;
    __shared__ float xs[4][11];
    bool ok = n < N;
    if (ok && o < 11) xs[sub][o] = x[n * 11 + o];
    if (ok && o == 0) g_deg[n] = 0.f;
    if (ok) g_agg[n * H + o] = 0.f;
    __syncthreads();
    if (ok) {
        float a = flb[o];
        #pragma unroll
        for (int i = 0; i < 11; i++) a += xs[sub][i] * flW[o * 11 + i];
        g_x[n * H + o] = siluf(a);
    }
}

// ---------------- init B: weight conversions/packs ---------------------------
__global__ void k_init_w(const float* __restrict__ W2,
                         const float* __restrict__ rootW,
                         const float* __restrict__ gWih,
                         const float* __restrict__ gWhh,
                         const float* __restrict__ lWih,
                         const float* __restrict__ lWhh) {
    int i = blockIdx.x * blockDim.x + threadIdx.x;
    if (i < HH * WID) g_W2H[i] = __float2half(W2[i]);
    if (i < 16 * 64) {            // rootP: [i4][o]
        int i4 = i >> 6, o = i & 63;
        const float* s = rootW + o * H + i4 * 4;
        g_rootP[i] = make_float4(s[0], s[1], s[2], s[3]);
    }
    if (i < 16 * 3 * 64) {        // giP/ghP: [i4][g][o]
        int o = i & 63, g = (i >> 6) % 3, i4 = i / 192;
        const float* s1 = gWih + (g * 64 + o) * H + i4 * 4;
        g_giP[i] = make_float4(s1[0], s1[1], s1[2], s1[3]);
        const float* s2 = gWhh + (g * 64 + o) * H + i4 * 4;
        g_ghP[i] = make_float4(s2[0], s2[1], s2[2], s2[3]);
    }
    if (i < LST4 * 2 * H) { int r = i >> 7, c = i & 127; g_lstmWihT[c * LST4 + r] = lWih[i]; }
    if (i < LST4 * H)     { int r = i >> 6, c = i & 63;  g_lstmWhhT[c * LST4 + r] = lWhh[i]; }
}

// ---------------- edge MLP hidden (fp16) + degree: warp per edge -------------
__global__ void k_edge_hidden(const int* __restrict__ ei, const float* __restrict__ ea,
                              const float* __restrict__ pos, const float* __restrict__ W1,
                              const float* __restrict__ b1, int E) {
    int w = threadIdx.x >> 5, lane = threadIdx.x & 31;
    int e = blockIdx.x * 8 + w;
    if (e >= E) return;
    int s = ei[e], d = ei[E + e];
    if (lane == 0) atomicAdd(&g_deg[d], 1.f);
    float ef0 = ea[e * 4 + 0], ef1 = ea[e * 4 + 1];
    float ef2 = ea[e * 4 + 2], ef3 = ea[e * 4 + 3];
    float dx = pos[s * 3 + 0] - pos[d * 3 + 0];
    float dy = pos[s * 3 + 1] - pos[d * 3 + 1];
    float dz = pos[s * 3 + 2] - pos[d * 3 + 2];
    float ef4 = sqrtf(dx * dx + dy * dy + dz * dz);
    #pragma unroll
    for (int q = 0; q < 4; q++) {
        int o = q * 32 + lane;
        const float* wr = W1 + o * 5;
        float a = b1[o] + ef0 * wr[0] + ef1 * wr[1] + ef2 * wr[2] + ef3 * wr[3] + ef4 * wr[4];
        g_hidH[(size_t)e * WID + o] = __float2half(siluf(a));
    }
}

// ---------------- W_edge GEMM via mma.sync fp16 ------------------------------
__global__ __launch_bounds__(256, 2) void k_wedge_mma(const float* __restrict__ bias, int E) {
    extern __shared__ char smem[];
    uint32_t sb = smem_to_u32(smem);
    int tid = threadIdx.x, lane = tid & 31, wid = tid >> 5;
    int et = blockIdx.x;
    int e0 = et * 128;
    int Ibase = blockIdx.y * (32 / JSPLIT);

    #pragma unroll
    for (int q = 0; q < 8; q++) {
        int idx = q * 256 + tid;
        int r = idx >> 4, ch = idx & 15;
        uint4 v = *(const uint4*)(g_hidH + (size_t)(e0 + r) * WID + ch * 8);
        *(uint4*)(smem + OFFA + r * 272 + ch * 16) = v;
    }
    #pragma unroll
    for (int q = 0; q < 8; q++) {
        int idx = q * 256 + tid;
        int r = idx >> 4, ch = idx & 15;
        CP_ASYNC16(sb + OFFB(0) + r * 272 + ch * 16,
                   g_W2H + (size_t)(Ibase * 128 + r) * WID + ch * 8);
    }
    CP_COMMIT();

    int m0w = (wid >> 2) * 64, n0w = (wid & 3) * 32;
    uint32_t a_off = (uint32_t)(m0w + (lane & 15)) * 272 + (uint32_t)(lane >> 4) * 16;
    uint32_t b_off = (uint32_t)(n0w + (lane & 7)) * 272 + (uint32_t)((lane >> 3) & 1) * 16;

    for (int it = 0; it < 32 / JSPLIT; it++) {
        int I = Ibase + it;
        int cur = it & 1;
        if (it + 1 < 32 / JSPLIT) {
            int j1 = (I + 1) * 128;
            #pragma unroll
            for (int q = 0; q < 8; q++) {
                int idx = q * 256 + tid;
                int r = idx >> 4, ch = idx & 15;
                CP_ASYNC16(sb + OFFB((it + 1) & 1) + r * 272 + ch * 16,
                           g_W2H + (size_t)(j1 + r) * WID + ch * 8);
            }
            CP_COMMIT();
            CP_WAIT1();
        } else {
            CP_WAIT0();
        }
        __syncthreads();

        float c[4][4][4];
        #pragma unroll
        for (int mf = 0; mf < 4; mf++)
            #pragma unroll
            for (int nf = 0; nf < 4; nf++) {
                c[mf][nf][0] = 0.f; c[mf][nf][1] = 0.f; c[mf][nf][2] = 0.f; c[mf][nf][3] = 0.f;
            }
        uint32_t aB = sb + OFFA + a_off;
        uint32_t bB = sb + OFFB(cur) + b_off;

        #pragma unroll
        for (int ks = 0; ks < 8; ks++) {
            uint32_t koff = (uint32_t)ks * 32;
            uint32_t af[4][4], bf[4][2];
            #pragma unroll
            for (int mf = 0; mf < 4; mf++) LDSM_X4(af[mf], aB + mf * (16 * 272) + koff);
            #pragma unroll
            for (int nf = 0; nf < 4; nf++) LDSM_X2(bf[nf], bB + nf * (8 * 272) + koff);
            #pragma unroll
            for (int mf = 0; mf < 4; mf++)
                #pragma unroll
                for (int nf = 0; nf < 4; nf++) MMA_F16(c[mf][nf], af[mf], bf[nf]);
        }

        int j0 = I * 128;
        float bv[8];
        #pragma unroll
        for (int k = 0; k < 8; k++)
            bv[k] = __ldg(&bias[j0 + n0w + (k & 3) * 8 + (lane & 3) * 2 + (k >> 2)]);
        __half* base = g_WedgeH + ((((size_t)(et * 32 + I) * 8 + wid) * 8) * 32 + lane) * 8;
        #pragma unroll
        for (int mf = 0; mf < 4; mf++) {
            #pragma unroll
            for (int h = 0; h < 2; h++) {
                __half2 p0 = __floats2half2_rn(c[mf][0][h * 2] + bv[0], c[mf][1][h * 2] + bv[1]);
                __half2 p1 = __floats2half2_rn(c[mf][2][h * 2] + bv[2], c[mf][3][h * 2] + bv[3]);
                __half2 p2 = __floats2half2_rn(c[mf][0][h * 2 + 1] + bv[4], c[mf][1][h * 2 + 1] + bv[5]);
                __half2 p3 = __floats2half2_rn(c[mf][2][h * 2 + 1] + bv[6], c[mf][3][h * 2 + 1] + bv[7]);
                uint4 u = make_uint4(*(uint32_t*)&p0, *(uint32_t*)&p1, *(uint32_t*)&p2, *(uint32_t*)&p3);
                *(uint4*)(base + (size_t)(mf * 2 + h) * 32 * 8) = u;
            }
        }
        __syncthreads();
    }
}

// ---------------- message pass: agg[dst] += x[src] @ W_e ---------------------
__global__ __launch_bounds__(256, 6) void k_message(const int* __restrict__ ei, int E) {
    int w = threadIdx.x >> 5, lane = threadIdx.x & 31;
    int e = blockIdx.x * 8 + w;
    __shared__ float xs[8][H];
    if (e >= E) return;
    int s = ei[e], d = ei[E + e];
    xs[w][lane] = g_x[s * H + lane];
    xs[w][lane + 32] = g_x[s * H + 32 + lane];
    __syncwarp();

    int et = e >> 7, r = e & 127;
    int widm = r >> 6, mf = (r >> 4) & 3, h = (r >> 3) & 1, r7 = r & 7;
    int pp = lane >> 4, widn = (lane >> 2) & 3, cp = lane & 3;
    int ihalf = widn >> 1;
    int olow = widn & 1;

    const __half* bp = g_WedgeH +
        (((((size_t)et * 32) * 8 + widm * 4 + widn) * 8 + mf * 2 + h) * 32 + r7 * 4 + cp) * 8;
    const size_t iterStride = (size_t)8 * 8 * 32 * 8;

    float acc[8];
    #pragma unroll
    for (int k = 0; k < 8; k++) acc[k] = 0.f;

    #pragma unroll
    for (int st = 0; st < 16; st++) {
        int iter = st * 2 + pp;
        uint4 v = __ldcs((const uint4*)(bp + (size_t)iter * iterStride));
        float xi = xs[w][iter * 2 + ihalf];
        float2 f0 = __half22float2(*(__half2*)&v.x);
        float2 f1 = __half22float2(*(__half2*)&v.y);
        float2 f2 = __half22float2(*(__half2*)&v.z);
        float2 f3 = __half22float2(*(__half2*)&v.w);
        acc[0] += xi * f0.x; acc[1] += xi * f0.y;
        acc[2] += xi * f1.x; acc[3] += xi * f1.y;
        acc[4] += xi * f2.x; acc[5] += xi * f2.y;
        acc[6] += xi * f3.x; acc[7] += xi * f3.y;
    }
    #pragma unroll
    for (int k = 0; k < 8; k++) {
        acc[k] += __shfl_xor_sync(0xffffffffu, acc[k], 8);
        acc[k] += __shfl_xor_sync(0xffffffffu, acc[k], 16);
    }
    int nf = pp * 2 + ihalf;
    int o = olow * 32 + nf * 8 + cp * 2;
    atomicAdd(&g_agg[d * H + o], acc[nf]);
    atomicAdd(&g_agg[d * H + o + 1], acc[nf + 4]);
}

// ---------------- combine + GRU cell (vectorized packed weights) -------------
__global__ void k_combine_gru(const float* __restrict__ rb, const float* __restrict__ bih,
                              const float* __restrict__ bhh, int N) {
    int sub = threadIdx.x >> 6, o = threadIdx.x & 63;
    int n = blockIdx.x * 4 + sub;
    __shared__ __align__(16) float xs[4][H];
    __shared__ __align__(16) float xcs[4][H];
    bool ok = n < N;
    float xo = 0.f;
    if (ok) { xo = g_x[n * H + o]; xs[sub][o] = xo; }
    __syncthreads();
    if (ok) {
        float dg = g_deg[n]; if (dg < 1.f) dg = 1.f;
        float a = rb[o] + g_agg[n * H + o] / dg;
        g_agg[n * H + o] = 0.f;  // reset for next layer's atomics
        const float4* xs4 = (const float4*)xs[sub];
        #pragma unroll 4
        for (int i4 = 0; i4 < 16; i4++) {
            float4 w = g_rootP[i4 * 64 + o];
            float4 xq = xs4[i4];
            a += xq.x * w.x + xq.y * w.y + xq.z * w.z + xq.w * w.w;
        }
        xcs[sub][o] = siluf(a);
    }
    __syncthreads();
    if (ok) {
        float gi0 = bih[o], gi1 = bih[64 + o], gi2 = bih[128 + o];
        float gh0 = bhh[o], gh1 = bhh[64 + o], gh2 = bhh[128 + o];
        const float4* xs4 = (const float4*)xs[sub];
        const float4* xc4 = (const float4*)xcs[sub];
        #pragma unroll 4
        for (int i4 = 0; i4 < 16; i4++) {
            float4 xq = xc4[i4], hq = xs4[i4];
            float4 w0 = g_giP[(i4 * 3 + 0) * 64 + o];
            float4 w1 = g_giP[(i4 * 3 + 1) * 64 + o];
            float4 w2 = g_giP[(i4 * 3 + 2) * 64 + o];
            float4 v0 = g_ghP[(i4 * 3 + 0) * 64 + o];
            float4 v1 = g_ghP[(i4 * 3 + 1) * 64 + o];
            float4 v2 = g_ghP[(i4 * 3 + 2) * 64 + o];
            gi0 += xq.x * w0.x + xq.y * w0.y + xq.z * w0.z + xq.w * w0.w;
            gi1 += xq.x * w1.x + xq.y * w1.y + xq.z * w1.z + xq.w * w1.w;
            gi2 += xq.x * w2.x + xq.y * w2.y + xq.z * w2.z + xq.w * w2.w;
            gh0 += hq.x * v0.x + hq.y * v0.y + hq.z * v0.z + hq.w * v0.w;
            gh1 += hq.x * v1.x + hq.y * v1.y + hq.z * v1.z + hq.w * v1.w;
            gh2 += hq.x * v2.x + hq.y * v2.y + hq.z * v2.z + hq.w * v2.w;
        }
        float r = sigm(gi0 + gh0);
        float z = sigm(gi1 + gh1);
        float nn = tanhf(gi2 + r * gh2);
        g_x[n * H + o] = (1.f - z) * nn + z * xo;
    }
}

// ---------------- fused Set2Set readout + output head (1 block per graph) ----
__global__ __launch_bounds__(256) void k_readout(
        const int* __restrict__ batch,
        const float* __restrict__ lbih, const float* __restrict__ lbhh,
        const float* __restrict__ oW1, const float* __restrict__ ob1,
        const float* __restrict__ oW2, const float* __restrict__ ob2,
        float* __restrict__ out, int N) {
    int b = blockIdx.x, t = threadIdx.x;  // 256 threads
    __shared__ float qs[128], hs[64], cs[64], gs[256], red[256];
    __shared__ float ea[1024];
    __shared__ int sseg[2];
    if (t < 2) {
        int target = b + t;
        int lo = 0, hi = N;
        while (lo < hi) { int m = (lo + hi) >> 1; if (batch[m] < target) lo = m + 1; else hi = m; }
        sseg[t] = lo;
    }
    if (t < 128) qs[t] = 0.f;
    if (t < 64) { hs[t] = 0.f; cs[t] = 0.f; }
    __syncthreads();
    int s = sseg[0], en = sseg[1], cnt = en - s;

    for (int step = 0; step < 3; step++) {
        float g = lbih[t] + lbhh[t];
        #pragma unroll 8
        for (int i = 0; i < 128; i++) g += qs[i] * g_lstmWihT[i * LST4 + t];
        #pragma unroll 8
        for (int i = 0; i < 64; i++)  g += hs[i] * g_lstmWhhT[i * LST4 + t];
        gs[t] = g;
        __syncthreads();
        if (t < 64) {
            float ig = sigm(gs[t]), fg = sigm(gs[64 + t]);
            float gg = tanhf(gs[128 + t]), og = sigm(gs[192 + t]);
            float c = fg * cs[t] + ig * gg;
            cs[t] = c;
            hs[t] = og * tanhf(c);
        }
        __syncthreads();
        int w = t >> 5, lane = t & 31;
        for (int n = s + w; n < en; n += 8) {
            float v = g_x[n * 64 + lane] * hs[lane] + g_x[n * 64 + 32 + lane] * hs[32 + lane];
            #pragma unroll
            for (int off = 16; off; off >>= 1) v += __shfl_xor_sync(0xffffffffu, v, off);
            if (lane == 0) ea[n - s] = v;
        }
        __syncthreads();
        float mx = -3.4e38f;
        for (int n = t; n < cnt; n += 256) mx = fmaxf(mx, ea[n]);
        red[t] = mx; __syncthreads();
        for (int off = 128; off; off >>= 1) { if (t < off) red[t] = fmaxf(red[t], red[t + off]); __syncthreads(); }
        mx = red[0]; __syncthreads();
        float sm = 0.f;
        for (int n = t; n < cnt; n += 256) { float av = expf(ea[n] - mx); ea[n] = av; sm += av; }
        red[t] = sm; __syncthreads();
        for (int off = 128; off; off >>= 1) { if (t < off) red[t] += red[t + off]; __syncthreads(); }
        float den = red[0];
        __syncthreads();
        if (t < 64) {
            float r = 0.f;
            for (int n = 0; n < cnt; n++) r += ea[n] * g_x[(s + n) * 64 + t];
            qs[64 + t] = (cnt > 0) ? r / den : 0.f;
            qs[t] = hs[t];
        }
        __syncthreads();
    }
    if (t < 64) {
        float a = ob1[t];
        #pragma unroll 8
        for (int i = 0; i < 128; i++) a += qs[i] * oW1[t * 128 + i];
        red[t] = siluf(a) * oW2[t];
    }
    __syncthreads();
    if (t < 32) {
        float v = red[t] + red[t + 32];
        #pragma unroll
        for (int off = 16; off; off >>= 1) v += __shfl_xor_sync(0xffffffffu, v, off);
        if (t == 0) out[b] = v + ob2[0];
    }
}

// ---------------- host launcher ----------------------------------------------
extern "C" void kernel_launch(void* const* d_in, const int* in_sizes, int n_in,
                              void* d_out, int out_size) {
    const float* x = (const float*)d_in[0];
    int N = in_sizes[0] / 11;
    bool dictOrder = (in_sizes[2] == 3 * N);
    const int*   ei  = (const int*)  d_in[dictOrder ? 3 : 1];
    const float* ea  = (const float*)d_in[dictOrder ? 1 : 2];
    const float* pos = (const float*)d_in[dictOrder ? 2 : 3];
    const int*   batch = (const int*)d_in[4];
    int E = in_sizes[dictOrder ? 3 : 1] / 2;
    int B = out_size;

    const float* fl_W  = (const float*)d_in[5];
    const float* fl_b  = (const float*)d_in[6];
    const float* nn_W1 = (const float*)d_in[7];
    const float* nn_b1 = (const float*)d_in[8];
    const float* nn_W2 = (const float*)d_in[9];
    const float* nn_b2 = (const float*)d_in[10];
    const float* root_W = (const float*)d_in[11];
    const float* root_b = (const float*)d_in[12];
    const float* gru_Wih = (const float*)d_in[13];
    const float* gru_Whh = (const float*)d_in[14];
    const float* gru_bih = (const float*)d_in[15];
    const float* gru_bhh = (const float*)d_in[16];
    const float* lstm_Wih = (const float*)d_in[17];
    const float* lstm_Whh = (const float*)d_in[18];
    const float* lstm_bih = (const float*)d_in[19];
    const float* lstm_bhh = (const float*)d_in[20];
    const float* out_W1 = (const float*)d_in[21];
    const float* out_b1 = (const float*)d_in[22];
    const float* out_W2 = (const float*)d_in[23];
    const float* out_b2 = (const float*)d_in[24];
    float* out = (float*)d_out;

    cudaFuncSetAttribute(k_wedge_mma, cudaFuncAttributeMaxDynamicSharedMemorySize, SMEM_WEDGE);

    k_init_node<<<(N + 3) / 4, 256>>>(x, fl_W, fl_b, N);                  // 0
    k_init_w<<<(HH * WID + 255) / 256, 256>>>(nn_W2, root_W, gru_Wih, gru_Whh, lstm_Wih, lstm_Whh); // 1
    k_edge_hidden<<<(E + 7) / 8, 256>>>(ei, ea, pos, nn_W1, nn_b1, E);    // 2
    dim3 gw((E + 127) / 128, JSPLIT);
    k_wedge_mma<<<gw, 256, SMEM_WEDGE>>>(nn_b2, E);                       // 3  <- profiled

    for (int l = 0; l < 4; l++) {
        k_message<<<(E + 7) / 8, 256>>>(ei, E);
        k_combine_gru<<<(N + 3) / 4, 256>>>(root_b, gru_bih, gru_bhh, N);
    }

    k_readout<<<B, 256>>>(batch, lstm_bih, lstm_bhh, out_W1, out_b1, out_W2, out_b2, out, N);
}

// round 14
// speedup vs baseline: 1.2971x; 1.2971x over previous
#include <cuda_runtime.h>
#include <cuda_fp16.h>
#include <math.h>
#include <stdint.h>

// ---------------- compile-time maxima (problem shapes are fixed) -------------
#define MAXN 10000
#define MAXE 50000
#define MAXB 512
#define H 64
#define HH 4096      // H*H
#define WID 128      // edge-MLP hidden width
#define GRU3 192     // 3*H
#define LST4 256     // 4*H
#define MAXTILES 391                      // ceil(MAXE/128)

// ---------------- device scratch (allocation-free rule: __device__ globals) --
// W_edge stored in mma-fragment order, 1 MB per 128-edge tile:
// half index = ((((tile*32 + I)*8 + wid)*8 + mf*2 + h)*32 + lane)*8 + k
__device__ __half g_WedgeH[(size_t)MAXTILES * 128 * HH];
__device__ __half g_hidH[(size_t)(MAXE + 128) * WID]; // edge MLP hidden fp16
__device__ __half g_W2H[HH * WID];                    // nn_W2 fp16
__device__ float g_x[MAXN * H];
__device__ float g_agg[MAXN * H];
__device__ float g_deg[MAXN];
// packed weights: float4 over 4 consecutive i for fixed output o (coalesced in o)
__device__ float4 g_rootP[16 * 64];           // [i4][o]
__device__ float4 g_giP[16 * 3 * 64];         // [i4][gate][o]
__device__ float4 g_ghP[16 * 3 * 64];
__device__ float g_lstmWihT[2 * H * LST4];
__device__ float g_lstmWhhT[H * LST4];

__device__ __forceinline__ float sigm(float v) { return 1.f / (1.f + expf(-v)); }
__device__ __forceinline__ float siluf(float v) { return v / (1.f + expf(-v)); }

__device__ __forceinline__ uint32_t smem_to_u32(const void* p) {
    uint32_t a;
    asm("{ .reg .u64 t; cvta.to.shared.u64 t, %1; cvt.u32.u64 %0, t; }" : "=r"(a) : "l"(p));
    return a;
}

// ---------------- mma.sync helpers -------------------------------------------
#define LDSM_X4(r, addr) \
    asm volatile("ldmatrix.sync.aligned.m8n8.x4.shared.b16 {%0,%1,%2,%3}, [%4];" \
        : "=r"((r)[0]), "=r"((r)[1]), "=r"((r)[2]), "=r"((r)[3]) : "r"(addr))
#define LDSM_X2(r, addr) \
    asm volatile("ldmatrix.sync.aligned.m8n8.x2.shared.b16 {%0,%1}, [%2];" \
        : "=r"((r)[0]), "=r"((r)[1]) : "r"(addr))
#define MMA_F16(c, a, b) \
    asm volatile("mma.sync.aligned.m16n8k16.row.col.f32.f16.f16.f32 " \
        "{%0,%1,%2,%3}, {%4,%5,%6,%7}, {%8,%9}, {%0,%1,%2,%3};" \
        : "+f"((c)[0]), "+f"((c)[1]), "+f"((c)[2]), "+f"((c)[3]) \
        : "r"((a)[0]), "r"((a)[1]), "r"((a)[2]), "r"((a)[3]), "r"((b)[0]), "r"((b)[1]))
#define CP_ASYNC16(s, g) \
    asm volatile("cp.async.cg.shared.global [%0], [%1], 16;" :: "r"(s), "l"(g))
#define CP_COMMIT() asm volatile("cp.async.commit_group;")
#define CP_WAIT1() asm volatile("cp.async.wait_group 1;" ::: "memory")
#define CP_WAIT0() asm volatile("cp.async.wait_group 0;" ::: "memory")

// smem geometry for the wedge GEMM (fp16, single product)
#define ATILE_B (128 * 136 * 2)        // 34816 B per 128x128 fp16 tile (272 B rows)
#define OFFA 0
#define OFFB(buf) (ATILE_B + (buf) * ATILE_B)
#define SMEM_WEDGE (3 * ATILE_B)       // 104448 B -> 2 CTAs/SM
#define JSPLIT 4                       // j-dim CTA split (8 iters each) — measured best

// ---------------- fused init: zeros + node embed + weight prep ---------------
__global__ void k_init(const float* __restrict__ x, const float* __restrict__ flW,
                       const float* __restrict__ flb,
                       const float* __restrict__ W2,
                       const float* __restrict__ rootW,
                       const float* __restrict__ gWih,
                       const float* __restrict__ gWhh,
                       const float* __restrict__ lWih,
                       const float* __restrict__ lWhh,
                       int N, int nodeBlocks) {
    if (blockIdx.x < (unsigned)nodeBlocks) {
        int sub = threadIdx.x >> 6, o = threadIdx.x & 63;
        int n = blockIdx.x * 4 + sub;
        __shared__ float xs[4][11];
        bool ok = n < N;
        if (ok && o < 11) xs[sub][o] = x[n * 11 + o];
        if (ok && o == 0) g_deg[n] = 0.f;
        if (ok) g_agg[n * H + o] = 0.f;
        __syncthreads();
        if (ok) {
            float a = flb[o];
            #pragma unroll
            for (int i = 0; i < 11; i++) a += xs[sub][i] * flW[o * 11 + i];
            g_x[n * H + o] = siluf(a);
        }
    } else {
        int i = (blockIdx.x - nodeBlocks) * blockDim.x + threadIdx.x;
        if (i < HH * WID) g_W2H[i] = __float2half(W2[i]);
        if (i < 16 * 64) {            // rootP: [i4][o]
            int i4 = i >> 6, o = i & 63;
            const float* s = rootW + o * H + i4 * 4;
            g_rootP[i] = make_float4(s[0], s[1], s[2], s[3]);
        }
        if (i < 16 * 3 * 64) {        // giP/ghP: [i4][g][o]
            int o = i & 63, g = (i >> 6) % 3, i4 = i / 192;
            const float* s1 = gWih + (g * 64 + o) * H + i4 * 4;
            g_giP[i] = make_float4(s1[0], s1[1], s1[2], s1[3]);
            const float* s2 = gWhh + (g * 64 + o) * H + i4 * 4;
            g_ghP[i] = make_float4(s2[0], s2[1], s2[2], s2[3]);
        }
        if (i < LST4 * 2 * H) { int r = i >> 7, c = i & 127; g_lstmWihT[c * LST4 + r] = lWih[i]; }
        if (i < LST4 * H)     { int r = i >> 6, c = i & 63;  g_lstmWhhT[c * LST4 + r] = lWhh[i]; }
    }
}

// ---------------- edge MLP hidden (fp16) + degree: warp per edge -------------
__global__ void k_edge_hidden(const int* __restrict__ ei, const float* __restrict__ ea,
                              const float* __restrict__ pos, const float* __restrict__ W1,
                              const float* __restrict__ b1, int E) {
    int w = threadIdx.x >> 5, lane = threadIdx.x & 31;
    int e = blockIdx.x * 8 + w;
    if (e >= E) return;
    int s = ei[e], d = ei[E + e];
    if (lane == 0) atomicAdd(&g_deg[d], 1.f);
    float ef0 = ea[e * 4 + 0], ef1 = ea[e * 4 + 1];
    float ef2 = ea[e * 4 + 2], ef3 = ea[e * 4 + 3];
    float dx = pos[s * 3 + 0] - pos[d * 3 + 0];
    float dy = pos[s * 3 + 1] - pos[d * 3 + 1];
    float dz = pos[s * 3 + 2] - pos[d * 3 + 2];
    float ef4 = sqrtf(dx * dx + dy * dy + dz * dz);
    #pragma unroll
    for (int q = 0; q < 4; q++) {
        int o = q * 32 + lane;
        const float* wr = W1 + o * 5;
        float a = b1[o] + ef0 * wr[0] + ef1 * wr[1] + ef2 * wr[2] + ef3 * wr[3] + ef4 * wr[4];
        g_hidH[(size_t)e * WID + o] = __float2half(siluf(a));
    }
}

// ---------------- W_edge GEMM via mma.sync fp16 ------------------------------
__global__ __launch_bounds__(256, 2) void k_wedge_mma(const float* __restrict__ bias, int E) {
    extern __shared__ char smem[];
    uint32_t sb = smem_to_u32(smem);
    int tid = threadIdx.x, lane = tid & 31, wid = tid >> 5;
    int et = blockIdx.x;
    int e0 = et * 128;
    int Ibase = blockIdx.y * (32 / JSPLIT);

    #pragma unroll
    for (int q = 0; q < 8; q++) {
        int idx = q * 256 + tid;
        int r = idx >> 4, ch = idx & 15;
        uint4 v = *(const uint4*)(g_hidH + (size_t)(e0 + r) * WID + ch * 8);
        *(uint4*)(smem + OFFA + r * 272 + ch * 16) = v;
    }
    #pragma unroll
    for (int q = 0; q < 8; q++) {
        int idx = q * 256 + tid;
        int r = idx >> 4, ch = idx & 15;
        CP_ASYNC16(sb + OFFB(0) + r * 272 + ch * 16,
                   g_W2H + (size_t)(Ibase * 128 + r) * WID + ch * 8);
    }
    CP_COMMIT();

    int m0w = (wid >> 2) * 64, n0w = (wid & 3) * 32;
    uint32_t a_off = (uint32_t)(m0w + (lane & 15)) * 272 + (uint32_t)(lane >> 4) * 16;
    uint32_t b_off = (uint32_t)(n0w + (lane & 7)) * 272 + (uint32_t)((lane >> 3) & 1) * 16;

    for (int it = 0; it < 32 / JSPLIT; it++) {
        int I = Ibase + it;
        int cur = it & 1;
        if (it + 1 < 32 / JSPLIT) {
            int j1 = (I + 1) * 128;
            #pragma unroll
            for (int q = 0; q < 8; q++) {
                int idx = q * 256 + tid;
                int r = idx >> 4, ch = idx & 15;
                CP_ASYNC16(sb + OFFB((it + 1) & 1) + r * 272 + ch * 16,
                           g_W2H + (size_t)(j1 + r) * WID + ch * 8);
            }
            CP_COMMIT();
            CP_WAIT1();
        } else {
            CP_WAIT0();
        }
        __syncthreads();

        float c[4][4][4];
        #pragma unroll
        for (int mf = 0; mf < 4; mf++)
            #pragma unroll
            for (int nf = 0; nf < 4; nf++) {
                c[mf][nf][0] = 0.f; c[mf][nf][1] = 0.f; c[mf][nf][2] = 0.f; c[mf][nf][3] = 0.f;
            }
        uint32_t aB = sb + OFFA + a_off;
        uint32_t bB = sb + OFFB(cur) + b_off;

        #pragma unroll
        for (int ks = 0; ks < 8; ks++) {
            uint32_t koff = (uint32_t)ks * 32;
            uint32_t af[4][4], bf[4][2];
            #pragma unroll
            for (int mf = 0; mf < 4; mf++) LDSM_X4(af[mf], aB + mf * (16 * 272) + koff);
            #pragma unroll
            for (int nf = 0; nf < 4; nf++) LDSM_X2(bf[nf], bB + nf * (8 * 272) + koff);
            #pragma unroll
            for (int mf = 0; mf < 4; mf++)
                #pragma unroll
                for (int nf = 0; nf < 4; nf++) MMA_F16(c[mf][nf], af[mf], bf[nf]);
        }

        int j0 = I * 128;
        float bv[8];
        #pragma unroll
        for (int k = 0; k < 8; k++)
            bv[k] = __ldg(&bias[j0 + n0w + (k & 3) * 8 + (lane & 3) * 2 + (k >> 2)]);
        __half* base = g_WedgeH + ((((size_t)(et * 32 + I) * 8 + wid) * 8) * 32 + lane) * 8;
        #pragma unroll
        for (int mf = 0; mf < 4; mf++) {
            #pragma unroll
            for (int h = 0; h < 2; h++) {
                __half2 p0 = __floats2half2_rn(c[mf][0][h * 2] + bv[0], c[mf][1][h * 2] + bv[1]);
                __half2 p1 = __floats2half2_rn(c[mf][2][h * 2] + bv[2], c[mf][3][h * 2] + bv[3]);
                __half2 p2 = __floats2half2_rn(c[mf][0][h * 2 + 1] + bv[4], c[mf][1][h * 2 + 1] + bv[5]);
                __half2 p3 = __floats2half2_rn(c[mf][2][h * 2 + 1] + bv[6], c[mf][3][h * 2 + 1] + bv[7]);
                uint4 u = make_uint4(*(uint32_t*)&p0, *(uint32_t*)&p1, *(uint32_t*)&p2, *(uint32_t*)&p3);
                *(uint4*)(base + (size_t)(mf * 2 + h) * 32 * 8) = u;
            }
        }
        __syncthreads();
    }
}

// ---------------- message pass: agg[dst] += x[src] @ W_e ---------------------
__global__ void k_message(const int* __restrict__ ei, int E) {
    int w = threadIdx.x >> 5, lane = threadIdx.x & 31;
    int e = blockIdx.x * 8 + w;
    __shared__ float xs[8][H];
    if (e >= E) return;
    int s = ei[e], d = ei[E + e];
    xs[w][lane] = g_x[s * H + lane];
    xs[w][lane + 32] = g_x[s * H + 32 + lane];
    __syncwarp();

    int et = e >> 7, r = e & 127;
    int widm = r >> 6, mf = (r >> 4) & 3, h = (r >> 3) & 1, r7 = r & 7;
    int pp = lane >> 4, widn = (lane >> 2) & 3, cp = lane & 3;
    int ihalf = widn >> 1;
    int olow = widn & 1;

    const __half* bp = g_WedgeH +
        (((((size_t)et * 32) * 8 + widm * 4 + widn) * 8 + mf * 2 + h) * 32 + r7 * 4 + cp) * 8;
    const size_t iterStride = (size_t)8 * 8 * 32 * 8;

    float acc[8];
    #pragma unroll
    for (int k = 0; k < 8; k++) acc[k] = 0.f;

    #pragma unroll
    for (int st = 0; st < 16; st++) {
        int iter = st * 2 + pp;
        uint4 v = *(const uint4*)(bp + (size_t)iter * iterStride);
        float xi = xs[w][iter * 2 + ihalf];
        float2 f0 = __half22float2(*(__half2*)&v.x);
        float2 f1 = __half22float2(*(__half2*)&v.y);
        float2 f2 = __half22float2(*(__half2*)&v.z);
        float2 f3 = __half22float2(*(__half2*)&v.w);
        acc[0] += xi * f0.x; acc[1] += xi * f0.y;
        acc[2] += xi * f1.x; acc[3] += xi * f1.y;
        acc[4] += xi * f2.x; acc[5] += xi * f2.y;
        acc[6] += xi * f3.x; acc[7] += xi * f3.y;
    }
    #pragma unroll
    for (int k = 0; k < 8; k++) {
        acc[k] += __shfl_xor_sync(0xffffffffu, acc[k], 8);
        acc[k] += __shfl_xor_sync(0xffffffffu, acc[k], 16);
    }
    int nf = pp * 2 + ihalf;
    int o = olow * 32 + nf * 8 + cp * 2;
    atomicAdd(&g_agg[d * H + o], acc[nf]);
    atomicAdd(&g_agg[d * H + o + 1], acc[nf + 4]);
}

// ---------------- combine + GRU cell (vectorized packed weights) -------------
__global__ void k_combine_gru(const float* __restrict__ rb, const float* __restrict__ bih,
                              const float* __restrict__ bhh, int N) {
    int sub = threadIdx.x >> 6, o = threadIdx.x & 63;
    int n = blockIdx.x * 4 + sub;
    __shared__ __align__(16) float xs[4][H];
    __shared__ __align__(16) float xcs[4][H];
    bool ok = n < N;
    float xo = 0.f;
    if (ok) { xo = g_x[n * H + o]; xs[sub][o] = xo; }
    __syncthreads();
    if (ok) {
        float dg = g_deg[n]; if (dg < 1.f) dg = 1.f;
        float a = rb[o] + g_agg[n * H + o] / dg;
        g_agg[n * H + o] = 0.f;  // reset for next layer's atomics
        const float4* xs4 = (const float4*)xs[sub];
        #pragma unroll 4
        for (int i4 = 0; i4 < 16; i4++) {
            float4 w = g_rootP[i4 * 64 + o];
            float4 xq = xs4[i4];
            a += xq.x * w.x + xq.y * w.y + xq.z * w.z + xq.w * w.w;
        }
        xcs[sub][o] = siluf(a);
    }
    __syncthreads();
    if (ok) {
        float gi0 = bih[o], gi1 = bih[64 + o], gi2 = bih[128 + o];
        float gh0 = bhh[o], gh1 = bhh[64 + o], gh2 = bhh[128 + o];
        const float4* xs4 = (const float4*)xs[sub];
        const float4* xc4 = (const float4*)xcs[sub];
        #pragma unroll 4
        for (int i4 = 0; i4 < 16; i4++) {
            float4 xq = xc4[i4], hq = xs4[i4];
            float4 w0 = g_giP[(i4 * 3 + 0) * 64 + o];
            float4 w1 = g_giP[(i4 * 3 + 1) * 64 + o];
            float4 w2 = g_giP[(i4 * 3 + 2) * 64 + o];
            float4 v0 = g_ghP[(i4 * 3 + 0) * 64 + o];
            float4 v1 = g_ghP[(i4 * 3 + 1) * 64 + o];
            float4 v2 = g_ghP[(i4 * 3 + 2) * 64 + o];
            gi0 += xq.x * w0.x + xq.y * w0.y + xq.z * w0.z + xq.w * w0.w;
            gi1 += xq.x * w1.x + xq.y * w1.y + xq.z * w1.z + xq.w * w1.w;
            gi2 += xq.x * w2.x + xq.y * w2.y + xq.z * w2.z + xq.w * w2.w;
            gh0 += hq.x * v0.x + hq.y * v0.y + hq.z * v0.z + hq.w * v0.w;
            gh1 += hq.x * v1.x + hq.y * v1.y + hq.z * v1.z + hq.w * v1.w;
            gh2 += hq.x * v2.x + hq.y * v2.y + hq.z * v2.z + hq.w * v2.w;
        }
        float r = sigm(gi0 + gh0);
        float z = sigm(gi1 + gh1);
        float nn = tanhf(gi2 + r * gh2);
        g_x[n * H + o] = (1.f - z) * nn + z * xo;
    }
}

// ---------------- fused Set2Set readout + output head (1 block per graph) ----
__global__ __launch_bounds__(256) void k_readout(
        const int* __restrict__ batch,
        const float* __restrict__ lbih, const float* __restrict__ lbhh,
        const float* __restrict__ oW1, const float* __restrict__ ob1,
        const float* __restrict__ oW2, const float* __restrict__ ob2,
        float* __restrict__ out, int N) {
    int b = blockIdx.x, t = threadIdx.x;  // 256 threads
    __shared__ float qs[128], hs[64], cs[64], gs[256], red[256];
    __shared__ float ea[1024];
    __shared__ int sseg[2];
    if (t < 2) {
        int target = b + t;
        int lo = 0, hi = N;
        while (lo < hi) { int m = (lo + hi) >> 1; if (batch[m] < target) lo = m + 1; else hi = m; }
        sseg[t] = lo;
    }
    if (t < 128) qs[t] = 0.f;
    if (t < 64) { hs[t] = 0.f; cs[t] = 0.f; }
    __syncthreads();
    int s = sseg[0], en = sseg[1], cnt = en - s;

    for (int step = 0; step < 3; step++) {
        float g = lbih[t] + lbhh[t];
        #pragma unroll 8
        for (int i = 0; i < 128; i++) g += qs[i] * g_lstmWihT[i * LST4 + t];
        #pragma unroll 8
        for (int i = 0; i < 64; i++)  g += hs[i] * g_lstmWhhT[i * LST4 + t];
        gs[t] = g;
        __syncthreads();
        if (t < 64) {
            float ig = sigm(gs[t]), fg = sigm(gs[64 + t]);
            float gg = tanhf(gs[128 + t]), og = sigm(gs[192 + t]);
            float c = fg * cs[t] + ig * gg;
            cs[t] = c;
            hs[t] = og * tanhf(c);
        }
        __syncthreads();
        int w = t >> 5, lane = t & 31;
        for (int n = s + w; n < en; n += 8) {
            float v = g_x[n * 64 + lane] * hs[lane] + g_x[n * 64 + 32 + lane] * hs[32 + lane];
            #pragma unroll
            for (int off = 16; off; off >>= 1) v += __shfl_xor_sync(0xffffffffu, v, off);
            if (lane == 0) ea[n - s] = v;
        }
        __syncthreads();
        float mx = -3.4e38f;
        for (int n = t; n < cnt; n += 256) mx = fmaxf(mx, ea[n]);
        red[t] = mx; __syncthreads();
        for (int off = 128; off; off >>= 1) { if (t < off) red[t] = fmaxf(red[t], red[t + off]); __syncthreads(); }
        mx = red[0]; __syncthreads();
        float sm = 0.f;
        for (int n = t; n < cnt; n += 256) { float av = expf(ea[n] - mx); ea[n] = av; sm += av; }
        red[t] = sm; __syncthreads();
        for (int off = 128; off; off >>= 1) { if (t < off) red[t] += red[t + off]; __syncthreads(); }
        float den = red[0];
        __syncthreads();
        if (t < 64) {
            float r = 0.f;
            for (int n = 0; n < cnt; n++) r += ea[n] * g_x[(s + n) * 64 + t];
            qs[64 + t] = (cnt > 0) ? r / den : 0.f;
            qs[t] = hs[t];
        }
        __syncthreads();
    }
    if (t < 64) {
        float a = ob1[t];
        #pragma unroll 8
        for (int i = 0; i < 128; i++) a += qs[i] * oW1[t * 128 + i];
        red[t] = siluf(a) * oW2[t];
    }
    __syncthreads();
    if (t < 32) {
        float v = red[t] + red[t + 32];
        #pragma unroll
        for (int off = 16; off; off >>= 1) v += __shfl_xor_sync(0xffffffffu, v, off);
        if (t == 0) out[b] = v + ob2[0];
    }
}

// ---------------- host launcher ----------------------------------------------
extern "C" void kernel_launch(void* const* d_in, const int* in_sizes, int n_in,
                              void* d_out, int out_size) {
    const float* x = (const float*)d_in[0];
    int N = in_sizes[0] / 11;
    bool dictOrder = (in_sizes[2] == 3 * N);
    const int*   ei  = (const int*)  d_in[dictOrder ? 3 : 1];
    const float* ea  = (const float*)d_in[dictOrder ? 1 : 2];
    const float* pos = (const float*)d_in[dictOrder ? 2 : 3];
    const int*   batch = (const int*)d_in[4];
    int E = in_sizes[dictOrder ? 3 : 1] / 2;
    int B = out_size;

    const float* fl_W  = (const float*)d_in[5];
    const float* fl_b  = (const float*)d_in[6];
    const float* nn_W1 = (const float*)d_in[7];
    const float* nn_b1 = (const float*)d_in[8];
    const float* nn_W2 = (const float*)d_in[9];
    const float* nn_b2 = (const float*)d_in[10];
    const float* root_W = (const float*)d_in[11];
    const float* root_b = (const float*)d_in[12];
    const float* gru_Wih = (const float*)d_in[13];
    const float* gru_Whh = (const float*)d_in[14];
    const float* gru_bih = (const float*)d_in[15];
    const float* gru_bhh = (const float*)d_in[16];
    const float* lstm_Wih = (const float*)d_in[17];
    const float* lstm_Whh = (const float*)d_in[18];
    const float* lstm_bih = (const float*)d_in[19];
    const float* lstm_bhh = (const float*)d_in[20];
    const float* out_W1 = (const float*)d_in[21];
    const float* out_b1 = (const float*)d_in[22];
    const float* out_W2 = (const float*)d_in[23];
    const float* out_b2 = (const float*)d_in[24];
    float* out = (float*)d_out;

    cudaFuncSetAttribute(k_wedge_mma, cudaFuncAttributeMaxDynamicSharedMemorySize, SMEM_WEDGE);

    int nodeBlocks = (N + 3) / 4;
    int wBlocks = (HH * WID + 255) / 256;
    k_init<<<nodeBlocks + wBlocks, 256>>>(x, fl_W, fl_b, nn_W2, root_W,
                                          gru_Wih, gru_Whh, lstm_Wih, lstm_Whh,
                                          N, nodeBlocks);                 // 0
    k_edge_hidden<<<(E + 7) / 8, 256>>>(ei, ea, pos, nn_W1, nn_b1, E);    // 1
    dim3 gw((E + 127) / 128, JSPLIT);
    k_wedge_mma<<<gw, 256, SMEM_WEDGE>>>(nn_b2, E);                       // 2

    for (int l = 0; l < 4; l++) {
        k_message<<<(E + 7) / 8, 256>>>(ei, E);                           // 3 (l=0) <- profiled
        k_combine_gru<<<(N + 3) / 4, 256>>>(root_b, gru_bih, gru_bhh, N);
    }

    k_readout<<<B, 256>>>(batch, lstm_bih, lstm_bhh, out_W1, out_b1, out_W2, out_b2, out, N);
}

// round 15
// speedup vs baseline: 1.3488x; 1.0399x over previous
#include <cuda_runtime.h>
#include <cuda_fp16.h>
#include <math.h>
#include <stdint.h>

// ---------------- compile-time maxima (problem shapes are fixed) -------------
#define MAXN 10000
#define MAXE 50000
#define MAXB 512
#define H 64
#define HH 4096      // H*H
#define WID 128      // edge-MLP hidden width
#define GRU3 192     // 3*H
#define LST4 256     // 4*H
#define MAXTILES 391                      // ceil(MAXE/128)

// ---------------- device scratch (allocation-free rule: __device__ globals) --
// W_edge stored in mma-fragment order, 1 MB per 128-edge tile:
// half index = ((((tile*32 + I)*8 + wid)*8 + mf*2 + h)*32 + lane)*8 + k
__device__ __half g_WedgeH[(size_t)MAXTILES * 128 * HH];
__device__ __half g_hidH[(size_t)(MAXE + 128) * WID]; // edge MLP hidden fp16
__device__ __half g_W2H[HH * WID];                    // nn_W2 fp16
__device__ float g_x[MAXN * H];
__device__ float g_agg[MAXN * H];
__device__ float g_deg[MAXN];
// packed weights: float4 over 4 consecutive i for fixed output o (coalesced in o)
__device__ float4 g_rootP[16 * 64];           // [i4][o]
__device__ float4 g_giP[16 * 3 * 64];         // [i4][gate][o]
__device__ float4 g_ghP[16 * 3 * 64];
__device__ float g_lstmWihT[2 * H * LST4];
__device__ float g_lstmWhhT[H * LST4];

__device__ __forceinline__ float sigm(float v) { return 1.f / (1.f + expf(-v)); }
__device__ __forceinline__ float siluf(float v) { return v / (1.f + expf(-v)); }

__device__ __forceinline__ uint32_t smem_to_u32(const void* p) {
    uint32_t a;
    asm("{ .reg .u64 t; cvta.to.shared.u64 t, %1; cvt.u32.u64 %0, t; }" : "=r"(a) : "l"(p));
    return a;
}

// ---------------- mma.sync helpers -------------------------------------------
#define LDSM_X4(r, addr) \
    asm volatile("ldmatrix.sync.aligned.m8n8.x4.shared.b16 {%0,%1,%2,%3}, [%4];" \
        : "=r"((r)[0]), "=r"((r)[1]), "=r"((r)[2]), "=r"((r)[3]) : "r"(addr))
#define LDSM_X2(r, addr) \
    asm volatile("ldmatrix.sync.aligned.m8n8.x2.shared.b16 {%0,%1}, [%2];" \
        : "=r"((r)[0]), "=r"((r)[1]) : "r"(addr))
#define MMA_F16(c, a, b) \
    asm volatile("mma.sync.aligned.m16n8k16.row.col.f32.f16.f16.f32 " \
        "{%0,%1,%2,%3}, {%4,%5,%6,%7}, {%8,%9}, {%0,%1,%2,%3};" \
        : "+f"((c)[0]), "+f"((c)[1]), "+f"((c)[2]), "+f"((c)[3]) \
        : "r"((a)[0]), "r"((a)[1]), "r"((a)[2]), "r"((a)[3]), "r"((b)[0]), "r"((b)[1]))
#define CP_ASYNC16(s, g) \
    asm volatile("cp.async.cg.shared.global [%0], [%1], 16;" :: "r"(s), "l"(g))
#define CP_COMMIT() asm volatile("cp.async.commit_group;")
#define CP_WAIT1() asm volatile("cp.async.wait_group 1;" ::: "memory")
#define CP_WAIT0() asm volatile("cp.async.wait_group 0;" ::: "memory")

// smem geometry for the wedge GEMM (fp16, single product)
#define ATILE_B (128 * 136 * 2)        // 34816 B per 128x128 fp16 tile (272 B rows)
#define OFFA 0
#define OFFB(buf) (ATILE_B + (buf) * ATILE_B)
#define SMEM_WEDGE (3 * ATILE_B)       // 104448 B -> 2 CTAs/SM
#define JSPLIT 4                       // j-dim CTA split (8 iters each) — measured best

// ---------------- fused init: zeros + node embed + weight prep ---------------
__global__ void k_init(const float* __restrict__ x, const float* __restrict__ flW,
                       const float* __restrict__ flb,
                       const float* __restrict__ W2,
                       const float* __restrict__ rootW,
                       const float* __restrict__ gWih,
                       const float* __restrict__ gWhh,
                       const float* __restrict__ lWih,
                       const float* __restrict__ lWhh,
                       int N, int nodeBlocks) {
    if (blockIdx.x < (unsigned)nodeBlocks) {
        int sub = threadIdx.x >> 6, o = threadIdx.x & 63;
        int n = blockIdx.x * 4 + sub;
        __shared__ float xs[4][11];
        bool ok = n < N;
        if (ok && o < 11) xs[sub][o] = x[n * 11 + o];
        if (ok && o == 0) g_deg[n] = 0.f;
        if (ok) g_agg[n * H + o] = 0.f;
        __syncthreads();
        if (ok) {
            float a = flb[o];
            #pragma unroll
            for (int i = 0; i < 11; i++) a += xs[sub][i] * flW[o * 11 + i];
            g_x[n * H + o] = siluf(a);
        }
    } else {
        int i = (blockIdx.x - nodeBlocks) * blockDim.x + threadIdx.x;
        if (i < HH * WID) g_W2H[i] = __float2half(W2[i]);
        if (i < 16 * 64) {            // rootP: [i4][o]
            int i4 = i >> 6, o = i & 63;
            const float* s = rootW + o * H + i4 * 4;
            g_rootP[i] = make_float4(s[0], s[1], s[2], s[3]);
        }
        if (i < 16 * 3 * 64) {        // giP/ghP: [i4][g][o]
            int o = i & 63, g = (i >> 6) % 3, i4 = i / 192;
            const float* s1 = gWih + (g * 64 + o) * H + i4 * 4;
            g_giP[i] = make_float4(s1[0], s1[1], s1[2], s1[3]);
            const float* s2 = gWhh + (g * 64 + o) * H + i4 * 4;
            g_ghP[i] = make_float4(s2[0], s2[1], s2[2], s2[3]);
        }
        if (i < LST4 * 2 * H) { int r = i >> 7, c = i & 127; g_lstmWihT[c * LST4 + r] = lWih[i]; }
        if (i < LST4 * H)     { int r = i >> 6, c = i & 63;  g_lstmWhhT[c * LST4 + r] = lWhh[i]; }
    }
}

// ---------------- edge MLP hidden (fp16) + degree: warp per edge -------------
__global__ void k_edge_hidden(const int* __restrict__ ei, const float* __restrict__ ea,
                              const float* __restrict__ pos, const float* __restrict__ W1,
                              const float* __restrict__ b1, int E) {
    int w = threadIdx.x >> 5, lane = threadIdx.x & 31;
    int e = blockIdx.x * 8 + w;
    if (e >= E) return;
    int s = ei[e], d = ei[E + e];
    if (lane == 0) atomicAdd(&g_deg[d], 1.f);
    float ef0 = ea[e * 4 + 0], ef1 = ea[e * 4 + 1];
    float ef2 = ea[e * 4 + 2], ef3 = ea[e * 4 + 3];
    float dx = pos[s * 3 + 0] - pos[d * 3 + 0];
    float dy = pos[s * 3 + 1] - pos[d * 3 + 1];
    float dz = pos[s * 3 + 2] - pos[d * 3 + 2];
    float ef4 = sqrtf(dx * dx + dy * dy + dz * dz);
    #pragma unroll
    for (int q = 0; q < 4; q++) {
        int o = q * 32 + lane;
        const float* wr = W1 + o * 5;
        float a = b1[o] + ef0 * wr[0] + ef1 * wr[1] + ef2 * wr[2] + ef3 * wr[3] + ef4 * wr[4];
        g_hidH[(size_t)e * WID + o] = __float2half(siluf(a));
    }
}

// ---------------- W_edge GEMM via mma.sync fp16 ------------------------------
__global__ __launch_bounds__(256, 2) void k_wedge_mma(const float* __restrict__ bias, int E) {
    extern __shared__ char smem[];
    uint32_t sb = smem_to_u32(smem);
    int tid = threadIdx.x, lane = tid & 31, wid = tid >> 5;
    int et = blockIdx.x;
    int e0 = et * 128;
    int Ibase = blockIdx.y * (32 / JSPLIT);

    #pragma unroll
    for (int q = 0; q < 8; q++) {
        int idx = q * 256 + tid;
        int r = idx >> 4, ch = idx & 15;
        uint4 v = *(const uint4*)(g_hidH + (size_t)(e0 + r) * WID + ch * 8);
        *(uint4*)(smem + OFFA + r * 272 + ch * 16) = v;
    }
    #pragma unroll
    for (int q = 0; q < 8; q++) {
        int idx = q * 256 + tid;
        int r = idx >> 4, ch = idx & 15;
        CP_ASYNC16(sb + OFFB(0) + r * 272 + ch * 16,
                   g_W2H + (size_t)(Ibase * 128 + r) * WID + ch * 8);
    }
    CP_COMMIT();

    int m0w = (wid >> 2) * 64, n0w = (wid & 3) * 32;
    uint32_t a_off = (uint32_t)(m0w + (lane & 15)) * 272 + (uint32_t)(lane >> 4) * 16;
    uint32_t b_off = (uint32_t)(n0w + (lane & 7)) * 272 + (uint32_t)((lane >> 3) & 1) * 16;

    for (int it = 0; it < 32 / JSPLIT; it++) {
        int I = Ibase + it;
        int cur = it & 1;
        if (it + 1 < 32 / JSPLIT) {
            int j1 = (I + 1) * 128;
            #pragma unroll
            for (int q = 0; q < 8; q++) {
                int idx = q * 256 + tid;
                int r = idx >> 4, ch = idx & 15;
                CP_ASYNC16(sb + OFFB((it + 1) & 1) + r * 272 + ch * 16,
                           g_W2H + (size_t)(j1 + r) * WID + ch * 8);
            }
            CP_COMMIT();
            CP_WAIT1();
        } else {
            CP_WAIT0();
        }
        __syncthreads();

        float c[4][4][4];
        #pragma unroll
        for (int mf = 0; mf < 4; mf++)
            #pragma unroll
            for (int nf = 0; nf < 4; nf++) {
                c[mf][nf][0] = 0.f; c[mf][nf][1] = 0.f; c[mf][nf][2] = 0.f; c[mf][nf][3] = 0.f;
            }
        uint32_t aB = sb + OFFA + a_off;
        uint32_t bB = sb + OFFB(cur) + b_off;

        #pragma unroll
        for (int ks = 0; ks < 8; ks++) {
            uint32_t koff = (uint32_t)ks * 32;
            uint32_t af[4][4], bf[4][2];
            #pragma unroll
            for (int mf = 0; mf < 4; mf++) LDSM_X4(af[mf], aB + mf * (16 * 272) + koff);
            #pragma unroll
            for (int nf = 0; nf < 4; nf++) LDSM_X2(bf[nf], bB + nf * (8 * 272) + koff);
            #pragma unroll
            for (int mf = 0; mf < 4; mf++)
                #pragma unroll
                for (int nf = 0; nf < 4; nf++) MMA_F16(c[mf][nf], af[mf], bf[nf]);
        }

        int j0 = I * 128;
        float bv[8];
        #pragma unroll
        for (int k = 0; k < 8; k++)
            bv[k] = __ldg(&bias[j0 + n0w + (k & 3) * 8 + (lane & 3) * 2 + (k >> 2)]);
        __half* base = g_WedgeH + ((((size_t)(et * 32 + I) * 8 + wid) * 8) * 32 + lane) * 8;
        #pragma unroll
        for (int mf = 0; mf < 4; mf++) {
            #pragma unroll
            for (int h = 0; h < 2; h++) {
                __half2 p0 = __floats2half2_rn(c[mf][0][h * 2] + bv[0], c[mf][1][h * 2] + bv[1]);
                __half2 p1 = __floats2half2_rn(c[mf][2][h * 2] + bv[2], c[mf][3][h * 2] + bv[3]);
                __half2 p2 = __floats2half2_rn(c[mf][0][h * 2 + 1] + bv[4], c[mf][1][h * 2 + 1] + bv[5]);
                __half2 p3 = __floats2half2_rn(c[mf][2][h * 2 + 1] + bv[6], c[mf][3][h * 2 + 1] + bv[7]);
                uint4 u = make_uint4(*(uint32_t*)&p0, *(uint32_t*)&p1, *(uint32_t*)&p2, *(uint32_t*)&p3);
                *(uint4*)(base + (size_t)(mf * 2 + h) * 32 * 8) = u;
            }
        }
        __syncthreads();
    }
}

// ---------------- message pass: agg[dst] += x[src] @ W_e ---------------------
__global__ void k_message(const int* __restrict__ ei, int E) {
    int w = threadIdx.x >> 5, lane = threadIdx.x & 31;
    int e = blockIdx.x * 8 + w;
    __shared__ float xs[8][H];
    if (e >= E) return;
    int s = ei[e], d = ei[E + e];
    xs[w][lane] = g_x[s * H + lane];
    xs[w][lane + 32] = g_x[s * H + 32 + lane];
    __syncwarp();

    int et = e >> 7, r = e & 127;
    int widm = r >> 6, mf = (r >> 4) & 3, h = (r >> 3) & 1, r7 = r & 7;
    int pp = lane >> 4, widn = (lane >> 2) & 3, cp = lane & 3;
    int ihalf = widn >> 1;
    int olow = widn & 1;

    const __half* bp = g_WedgeH +
        (((((size_t)et * 32) * 8 + widm * 4 + widn) * 8 + mf * 2 + h) * 32 + r7 * 4 + cp) * 8;
    const size_t iterStride = (size_t)8 * 8 * 32 * 8;

    float acc[8];
    #pragma unroll
    for (int k = 0; k < 8; k++) acc[k] = 0.f;

    #pragma unroll
    for (int st = 0; st < 16; st++) {
        int iter = st * 2 + pp;
        uint4 v = *(const uint4*)(bp + (size_t)iter * iterStride);
        float xi = xs[w][iter * 2 + ihalf];
        float2 f0 = __half22float2(*(__half2*)&v.x);
        float2 f1 = __half22float2(*(__half2*)&v.y);
        float2 f2 = __half22float2(*(__half2*)&v.z);
        float2 f3 = __half22float2(*(__half2*)&v.w);
        acc[0] += xi * f0.x; acc[1] += xi * f0.y;
        acc[2] += xi * f1.x; acc[3] += xi * f1.y;
        acc[4] += xi * f2.x; acc[5] += xi * f2.y;
        acc[6] += xi * f3.x; acc[7] += xi * f3.y;
    }
    #pragma unroll
    for (int k = 0; k < 8; k++) {
        acc[k] += __shfl_xor_sync(0xffffffffu, acc[k], 8);
        acc[k] += __shfl_xor_sync(0xffffffffu, acc[k], 16);
    }
    int nf = pp * 2 + ihalf;
    int o = olow * 32 + nf * 8 + cp * 2;
    atomicAdd(&g_agg[d * H + o], acc[nf]);
    atomicAdd(&g_agg[d * H + o + 1], acc[nf + 4]);
}

// ---------------- combine + GRU cell: 32 nodes/block, 8 nodes/thread ---------
// Thread (grp = tid>>6, o = tid&63) owns nodes n0 + grp*8 + j (j=0..7).
// Weight float4s loaded ONCE per i4 and applied to all 8 nodes (8x reuse).
__global__ __launch_bounds__(256) void k_combine_gru(
        const float* __restrict__ rb, const float* __restrict__ bih,
        const float* __restrict__ bhh, int N) {
    int o = threadIdx.x & 63, grp = threadIdx.x >> 6;
    int n0 = blockIdx.x * 32;
    __shared__ __align__(16) float xs[32][H];
    __shared__ __align__(16) float xcs[32][H];

    float xo[8];
    #pragma unroll
    for (int j = 0; j < 8; j++) {
        int n = n0 + grp * 8 + j;
        float v = (n < N) ? g_x[n * H + o] : 0.f;
        xo[j] = v;
        xs[grp * 8 + j][o] = v;
    }
    __syncthreads();

    // phase 1: xc = silu(rootW @ x + rb + agg/deg); reset agg
    float aacc[8];
    #pragma unroll
    for (int j = 0; j < 8; j++) {
        int n = n0 + grp * 8 + j;
        if (n < N) {
            float dg = g_deg[n]; if (dg < 1.f) dg = 1.f;
            aacc[j] = rb[o] + g_agg[n * H + o] / dg;
            g_agg[n * H + o] = 0.f;
        } else aacc[j] = 0.f;
    }
    #pragma unroll 4
    for (int i4 = 0; i4 < 16; i4++) {
        float4 w = g_rootP[i4 * 64 + o];
        #pragma unroll
        for (int j = 0; j < 8; j++) {
            float4 xq = ((const float4*)xs[grp * 8 + j])[i4];
            aacc[j] += xq.x * w.x + xq.y * w.y + xq.z * w.z + xq.w * w.w;
        }
    }
    #pragma unroll
    for (int j = 0; j < 8; j++) xcs[grp * 8 + j][o] = siluf(aacc[j]);
    __syncthreads();

    // phase 2: GRU gates. A=gi0+gh0, B=gi1+gh1, C=gi2, D=gh2 per node.
    float Ar[8], Br[8], Cr[8], Dr[8];
    {
        float a0 = bih[o] + bhh[o];
        float b0 = bih[64 + o] + bhh[64 + o];
        float c0 = bih[128 + o];
        float d0 = bhh[128 + o];
        #pragma unroll
        for (int j = 0; j < 8; j++) { Ar[j] = a0; Br[j] = b0; Cr[j] = c0; Dr[j] = d0; }
    }
    #pragma unroll 2
    for (int i4 = 0; i4 < 16; i4++) {
        float4 w0 = g_giP[(i4 * 3 + 0) * 64 + o];
        float4 w1 = g_giP[(i4 * 3 + 1) * 64 + o];
        float4 w2 = g_giP[(i4 * 3 + 2) * 64 + o];
        float4 v0 = g_ghP[(i4 * 3 + 0) * 64 + o];
        float4 v1 = g_ghP[(i4 * 3 + 1) * 64 + o];
        float4 v2 = g_ghP[(i4 * 3 + 2) * 64 + o];
        #pragma unroll
        for (int j = 0; j < 8; j++) {
            float4 xq = ((const float4*)xcs[grp * 8 + j])[i4];
            float4 hq = ((const float4*)xs[grp * 8 + j])[i4];
            Ar[j] += xq.x * w0.x + xq.y * w0.y + xq.z * w0.z + xq.w * w0.w
                   + hq.x * v0.x + hq.y * v0.y + hq.z * v0.z + hq.w * v0.w;
            Br[j] += xq.x * w1.x + xq.y * w1.y + xq.z * w1.z + xq.w * w1.w
                   + hq.x * v1.x + hq.y * v1.y + hq.z * v1.z + hq.w * v1.w;
            Cr[j] += xq.x * w2.x + xq.y * w2.y + xq.z * w2.z + xq.w * w2.w;
            Dr[j] += hq.x * v2.x + hq.y * v2.y + hq.z * v2.z + hq.w * v2.w;
        }
    }
    #pragma unroll
    for (int j = 0; j < 8; j++) {
        int n = n0 + grp * 8 + j;
        if (n < N) {
            float r = sigm(Ar[j]);
            float z = sigm(Br[j]);
            float nn = tanhf(Cr[j] + r * Dr[j]);
            g_x[n * H + o] = (1.f - z) * nn + z * xo[j];
        }
    }
}

// ---------------- fused Set2Set readout + output head (1 block per graph) ----
__global__ __launch_bounds__(256) void k_readout(
        const int* __restrict__ batch,
        const float* __restrict__ lbih, const float* __restrict__ lbhh,
        const float* __restrict__ oW1, const float* __restrict__ ob1,
        const float* __restrict__ oW2, const float* __restrict__ ob2,
        float* __restrict__ out, int N) {
    int b = blockIdx.x, t = threadIdx.x;  // 256 threads
    __shared__ float qs[128], hs[64], cs[64], gs[256], red[256];
    __shared__ float ea[1024];
    __shared__ int sseg[2];
    if (t < 2) {
        int target = b + t;
        int lo = 0, hi = N;
        while (lo < hi) { int m = (lo + hi) >> 1; if (batch[m] < target) lo = m + 1; else hi = m; }
        sseg[t] = lo;
    }
    if (t < 128) qs[t] = 0.f;
    if (t < 64) { hs[t] = 0.f; cs[t] = 0.f; }
    __syncthreads();
    int s = sseg[0], en = sseg[1], cnt = en - s;

    for (int step = 0; step < 3; step++) {
        float g = lbih[t] + lbhh[t];
        #pragma unroll 8
        for (int i = 0; i < 128; i++) g += qs[i] * g_lstmWihT[i * LST4 + t];
        #pragma unroll 8
        for (int i = 0; i < 64; i++)  g += hs[i] * g_lstmWhhT[i * LST4 + t];
        gs[t] = g;
        __syncthreads();
        if (t < 64) {
            float ig = sigm(gs[t]), fg = sigm(gs[64 + t]);
            float gg = tanhf(gs[128 + t]), og = sigm(gs[192 + t]);
            float c = fg * cs[t] + ig * gg;
            cs[t] = c;
            hs[t] = og * tanhf(c);
        }
        __syncthreads();
        int w = t >> 5, lane = t & 31;
        for (int n = s + w; n < en; n += 8) {
            float v = g_x[n * 64 + lane] * hs[lane] + g_x[n * 64 + 32 + lane] * hs[32 + lane];
            #pragma unroll
            for (int off = 16; off; off >>= 1) v += __shfl_xor_sync(0xffffffffu, v, off);
            if (lane == 0) ea[n - s] = v;
        }
        __syncthreads();
        float mx = -3.4e38f;
        for (int n = t; n < cnt; n += 256) mx = fmaxf(mx, ea[n]);
        red[t] = mx; __syncthreads();
        for (int off = 128; off; off >>= 1) { if (t < off) red[t] = fmaxf(red[t], red[t + off]); __syncthreads(); }
        mx = red[0]; __syncthreads();
        float sm = 0.f;
        for (int n = t; n < cnt; n += 256) { float av = expf(ea[n] - mx); ea[n] = av; sm += av; }
        red[t] = sm; __syncthreads();
        for (int off = 128; off; off >>= 1) { if (t < off) red[t] += red[t + off]; __syncthreads(); }
        float den = red[0];
        __syncthreads();
        if (t < 64) {
            float r = 0.f;
            for (int n = 0; n < cnt; n++) r += ea[n] * g_x[(s + n) * 64 + t];
            qs[64 + t] = (cnt > 0) ? r / den : 0.f;
            qs[t] = hs[t];
        }
        __syncthreads();
    }
    if (t < 64) {
        float a = ob1[t];
        #pragma unroll 8
        for (int i = 0; i < 128; i++) a += qs[i] * oW1[t * 128 + i];
        red[t] = siluf(a) * oW2[t];
    }
    __syncthreads();
    if (t < 32) {
        float v = red[t] + red[t + 32];
        #pragma unroll
        for (int off = 16; off; off >>= 1) v += __shfl_xor_sync(0xffffffffu, v, off);
        if (t == 0) out[b] = v + ob2[0];
    }
}

// ---------------- host launcher ----------------------------------------------
extern "C" void kernel_launch(void* const* d_in, const int* in_sizes, int n_in,
                              void* d_out, int out_size) {
    const float* x = (const float*)d_in[0];
    int N = in_sizes[0] / 11;
    bool dictOrder = (in_sizes[2] == 3 * N);
    const int*   ei  = (const int*)  d_in[dictOrder ? 3 : 1];
    const float* ea  = (const float*)d_in[dictOrder ? 1 : 2];
    const float* pos = (const float*)d_in[dictOrder ? 2 : 3];
    const int*   batch = (const int*)d_in[4];
    int E = in_sizes[dictOrder ? 3 : 1] / 2;
    int B = out_size;

    const float* fl_W  = (const float*)d_in[5];
    const float* fl_b  = (const float*)d_in[6];
    const float* nn_W1 = (const float*)d_in[7];
    const float* nn_b1 = (const float*)d_in[8];
    const float* nn_W2 = (const float*)d_in[9];
    const float* nn_b2 = (const float*)d_in[10];
    const float* root_W = (const float*)d_in[11];
    const float* root_b = (const float*)d_in[12];
    const float* gru_Wih = (const float*)d_in[13];
    const float* gru_Whh = (const float*)d_in[14];
    const float* gru_bih = (const float*)d_in[15];
    const float* gru_bhh = (const float*)d_in[16];
    const float* lstm_Wih = (const float*)d_in[17];
    const float* lstm_Whh = (const float*)d_in[18];
    const float* lstm_bih = (const float*)d_in[19];
    const float* lstm_bhh = (const float*)d_in[20];
    const float* out_W1 = (const float*)d_in[21];
    const float* out_b1 = (const float*)d_in[22];
    const float* out_W2 = (const float*)d_in[23];
    const float* out_b2 = (const float*)d_in[24];
    float* out = (float*)d_out;

    cudaFuncSetAttribute(k_wedge_mma, cudaFuncAttributeMaxDynamicSharedMemorySize, SMEM_WEDGE);

    int nodeBlocks = (N + 3) / 4;
    int wBlocks = (HH * WID + 255) / 256;
    k_init<<<nodeBlocks + wBlocks, 256>>>(x, fl_W, fl_b, nn_W2, root_W,
                                          gru_Wih, gru_Whh, lstm_Wih, lstm_Whh,
                                          N, nodeBlocks);                 // 0
    k_edge_hidden<<<(E + 7) / 8, 256>>>(ei, ea, pos, nn_W1, nn_b1, E);    // 1
    dim3 gw((E + 127) / 128, JSPLIT);
    k_wedge_mma<<<gw, 256, SMEM_WEDGE>>>(nn_b2, E);                       // 2

    for (int l = 0; l < 4; l++) {
        k_message<<<(E + 7) / 8, 256>>>(ei, E);                           // 3 (l=0) <- profiled
        k_combine_gru<<<(N + 31) / 32, 256>>>(root_b, gru_bih, gru_bhh, N);
    }

    k_readout<<<B, 256>>>(batch, lstm_bih, lstm_bhh, out_W1, out_b1, out_W2, out_b2, out, N);
}